// round 17
// baseline (speedup 1.0000x reference)
#include <cuda_runtime.h>
#include <cuda_bf16.h>

#define BB 512
#define LL 2048
#define CC 64
#define START_S 62
#define STOP_S 63
#define MID 1023

// scratch (no cudaMalloc allowed)
__device__ float g_part[BB];
__device__ float g_scores[BB];

// bf16x2 packed ops
__device__ __forceinline__ unsigned bffma(unsigned a, unsigned b, unsigned c) {
    unsigned d;
    asm("fma.rn.bf16x2 %0, %1, %2, %3;" : "=r"(d) : "r"(a), "r"(b), "r"(c));
    return d;
}
__device__ __forceinline__ unsigned bfadd(unsigned a, unsigned b) {
    unsigned d;
    asm("add.rn.bf16x2 %0, %1, %2;" : "=r"(d) : "r"(a), "r"(b));
    return d;
}
__device__ __forceinline__ float bfsum(unsigned ab) {
    float lo = __uint_as_float(ab << 16);
    float hi = __uint_as_float(ab & 0xffff0000u);
    return lo + hi;
}
__device__ __forceinline__ unsigned bfpack(float x, float y) {
    unsigned d;
    asm("cvt.rn.bf16x2.f32 %0, %1, %2;" : "=r"(d) : "f"(y), "f"(x));
    return d;
}

// two interleaved 64-dots in bf16x2 (this lane's two output states)
__device__ __forceinline__ void dot2(const unsigned* __restrict__ vsh32,
                                     const unsigned* __restrict__ eA,
                                     const unsigned* __restrict__ eB,
                                     float& ra, float& rb) {
    const uint4* q = reinterpret_cast<const uint4*>(vsh32);
    unsigned a0 = 0, a1 = 0, a2 = 0, a3 = 0;
    unsigned b0 = 0, b1 = 0, b2 = 0, b3 = 0;
#pragma unroll
    for (int j = 0; j < 8; ++j) {
        uint4 x = q[j];
        a0 = bffma(x.x, eA[4 * j + 0], a0);
        b0 = bffma(x.x, eB[4 * j + 0], b0);
        a1 = bffma(x.y, eA[4 * j + 1], a1);
        b1 = bffma(x.y, eB[4 * j + 1], b1);
        a2 = bffma(x.z, eA[4 * j + 2], a2);
        b2 = bffma(x.z, eB[4 * j + 2], b2);
        a3 = bffma(x.w, eA[4 * j + 3], a3);
        b3 = bffma(x.w, eB[4 * j + 3], b3);
    }
    ra = bfsum(bfadd(bfadd(a0, a1), bfadd(a2, a3)));
    rb = bfsum(bfadd(bfadd(b0, b1), bfadd(b2, b3)));
}

// forward step: v' = (e_t ⊙ (expT^T v)) ; MODE: 0 plain, 1 launch max, 2 renorm
template <int MODE>
__device__ __forceinline__ void stepF(float2 ev, float mkv,
                                      float& v0, float& v1, float& S, float& mx,
                                      int& cur, unsigned (*vsh)[32],
                                      const unsigned* __restrict__ eA,
                                      const unsigned* __restrict__ eB,
                                      int lane) {
    if (MODE == 1) {
        float x = fmaxf(v0, v1);
#pragma unroll
        for (int o = 16; o; o >>= 1) x = fmaxf(x, __shfl_xor_sync(0xffffffffu, x, o));
        mx = x;
    }
    float ee0 = __expf(ev.x);
    float ee1 = __expf(ev.y);
    float vr0 = v0, vr1 = v1;
    if (MODE == 2) {
        float r = __fdividef(1.0f, mx);
        S += __logf(mx);
        ee0 *= r; vr0 = v0 * r;
        ee1 *= r; vr1 = v1 * r;
    }
    float a, bq;
    dot2(vsh[cur], eA, eB, a, bq);
    float nv0 = (mkv > 0.f) ? a  * ee0 : vr0;
    float nv1 = (mkv > 0.f) ? bq * ee1 : vr1;
    v0 = nv0; v1 = nv1;
    vsh[cur ^ 1][lane] = bfpack(nv0, nv1);
    __syncwarp();
    cur ^= 1;
}

// backward step: w' = expT (e_{t+1} ⊙ w) ; emission applied BEFORE the dot
template <int MODE>
__device__ __forceinline__ void stepB(float2 ev, float mkv,
                                      float& v0, float& v1, float& S, float& mx,
                                      int& cur, unsigned (*vsh)[32],
                                      const unsigned* __restrict__ eA,
                                      const unsigned* __restrict__ eB,
                                      int lane) {
    if (MODE == 1) {
        float x = fmaxf(v0, v1);
#pragma unroll
        for (int o = 16; o; o >>= 1) x = fmaxf(x, __shfl_xor_sync(0xffffffffu, x, o));
        mx = x;
    }
    float ee0 = __expf(ev.x);
    float ee1 = __expf(ev.y);
    float vr0 = v0, vr1 = v1;
    if (MODE == 2) {
        float r = __fdividef(1.0f, mx);
        S += __logf(mx);
        ee0 *= r; vr0 = v0 * r;
        ee1 *= r; vr1 = v1 * r;
    }
    int nxt = cur ^ 1;
    vsh[nxt][lane] = bfpack(v0 * ee0, v1 * ee1);   // u = e⊙w (renorm folded in ee)
    __syncwarp();
    float a, bq;
    dot2(vsh[nxt], eA, eB, a, bq);
    v0 = (mkv > 0.f) ? a  : vr0;
    v1 = (mkv > 0.f) ? bq : vr1;
    cur = nxt;
}

// ---------------------------------------------------------------------------
// Bidirectional forward algorithm in exp-space, bf16 matvec, gold score fused
// as a 5th warp, and the exp(T) tables computed IN-KERNEL (prep_kernel gone —
// the one-time ~1K-cycle MUFU prologue hides under the 500K-cycle recursion).
// 256 CTAs x 160 threads = 2 batches/CTA:
//   warps 0-3: (fwd_b0, bwd_b0, fwd_b1, bwd_b1) on SMSPs 0-3;
//   warp 4  : exact fp32 gold score for both batches.
// Renorm every 8 steps (+ epilogue renorm in both directions so the final
// alpha·w product cannot overflow). Max-shuffles pipelined off the chain.
//   logZ = log( sum_c alpha_MID[c] * w_MID[c] ) + S_f + S_b.
// ---------------------------------------------------------------------------
__global__ void __launch_bounds__(160, 1) alpha_kernel(const float* __restrict__ em,
                                                       const float* __restrict__ Tm,
                                                       const float* __restrict__ mask,
                                                       const int* __restrict__ tags) {
    const int lane = threadIdx.x & 31;
    const int wid  = threadIdx.x >> 5;

    __shared__ __align__(16) unsigned vshbuf[4][2][32];  // [warp][buf][lane]
    __shared__ float warr[2][CC];
    __shared__ float sSb[2];

    if (wid == 4) {
        // ---------------- gold-score warp: both batches, exact fp32 ----------
#pragma unroll 1
        for (int pp = 0; pp < 2; ++pp) {
            const int bb = blockIdx.x * 2 + pp;
            const float* embS = em + (size_t)bb * (LL * CC);
            const float* mkbS = mask + (size_t)bb * LL;
            const int*   tgbS = tags + (size_t)bb * LL;
            float acc = 0.f, msum = 0.f;
#pragma unroll 1
            for (int t = lane; t < LL; t += 32) {
                float mval = mkbS[t];
                msum += mval;
                if (t >= 1) {
                    int tg = tgbS[t];
                    int tq = tgbS[t - 1];
                    acc += (embS[(size_t)t * CC + tg] + Tm[tq * CC + tg]) * mval;
                }
            }
#pragma unroll
            for (int o = 16; o; o >>= 1) {
                acc  += __shfl_xor_sync(0xffffffffu, acc, o);
                msum += __shfl_xor_sync(0xffffffffu, msum, o);
            }
            if (lane == 0) {
                int t0 = tgbS[0];
                float s = acc + embS[t0] + Tm[START_S * CC + t0];
                int last = (int)msum - 1;      // mask sum of 1.0s exact in fp32
                s += Tm[tgbS[last] * CC + STOP_S];
                g_scores[bb] = s;
            }
        }
        __syncthreads();
        return;
    }

    const int pair = wid >> 1;           // batch slot in CTA (0 or 1)
    const int dir  = wid & 1;            // 0 = forward, 1 = backward
    const int b    = blockIdx.x * 2 + pair;

    const float* emb = em + (size_t)b * (LL * CC);
    const float* mkb = mask + (size_t)b * LL;
    const float2* emb2 = reinterpret_cast<const float2*>(emb) + lane;

    unsigned (*vsh)[32] = vshbuf[wid];

    float v0, v1, S = 0.0f, mx = 0.0f;

    if (dir == 0) {
        // -------- forward half: steps 1..MID; eT computed in-kernel --------
        // eA[k]/eB[k] = bf16x2{ exp(T[k][2lane]), exp(T[k][2lane+1]) } column pair
        unsigned eA[32], eB[32];
        {
            const float2* t2 = reinterpret_cast<const float2*>(Tm) + lane;
#pragma unroll
            for (int k = 0; k < 32; ++k) {
                float2 r0 = t2[(size_t)(2 * k) * 32];        // row 2k, states (2lane,2lane+1)
                float2 r1 = t2[(size_t)(2 * k + 1) * 32];    // row 2k+1
                eA[k] = bfpack(__expf(r0.x), __expf(r1.x));  // {row2k, row2k+1} for state 2lane
                eB[k] = bfpack(__expf(r0.y), __expf(r1.y));  // ... for state 2lane+1
            }
        }
        {
            float2 ts = reinterpret_cast<const float2*>(Tm + START_S * CC)[lane];
            v0 = __expf(emb2[0].x + ts.x);
            v1 = __expf(emb2[0].y + ts.y);
        }
        vsh[0][lane] = bfpack(v0, v1);

        float2 ea = emb2[1 * 32], eb = emb2[2 * 32], ec = emb2[3 * 32];
        float  ma = mkb[1],       mb = mkb[2],       mc = mkb[3];
        __syncwarp();

        int cur = 0;
#define ADVF(t_)                                                        \
        {                                                               \
            int ti = (t_) + 3; if (ti > MID) ti = MID;                  \
            float2 en = emb2[(size_t)ti * 32];                          \
            float  mn = mkb[ti];                                        \
            ea = eb; ma = mb; eb = ec; mb = mc; ec = en; mc = mn;       \
        }
#define SF(MODE, t_)                                                    \
        {                                                               \
            float2 e0 = ea; float m0 = ma; ADVF(t_);                    \
            stepF<MODE>(e0, m0, v0, v1, S, mx, cur, vsh, eA, eB, lane); \
        }
        // 127 octets: steps 1..1016, renorm measured at 8k+1 / applied 8k+2
#pragma unroll 1
        for (int t = 1; t + 7 <= 1016; t += 8) {
            SF(1, t); SF(2, t + 1); SF(0, t + 2); SF(0, t + 3);
            SF(0, t + 4); SF(0, t + 5); SF(0, t + 6); SF(0, t + 7);
        }
        // tail: steps 1017..1023 with one more renorm to bound the window
        SF(1, 1017); SF(2, 1018);
#pragma unroll 1
        for (int t = 1019; t <= MID; ++t) { SF(0, t); }
#undef SF
#undef ADVF
        // epilogue renorm so the final alpha·w product cannot overflow
        {
            float x = fmaxf(v0, v1);
#pragma unroll
            for (int o = 16; o; o >>= 1) x = fmaxf(x, __shfl_xor_sync(0xffffffffu, x, o));
            float r = __fdividef(1.0f, x);
            v0 *= r; v1 *= r; S += __logf(x);
        }
    } else {
        // -------- backward half: steps L-2..MID; eT computed in-kernel -----
        // eA[k]/eB[k] = bf16x2{ exp(T[2lane][2k]), exp(T[2lane][2k+1]) } etc.
        unsigned eA[32], eB[32];
        {
            const float2* rowA = reinterpret_cast<const float2*>(Tm + (2 * lane) * CC);
            const float2* rowB = reinterpret_cast<const float2*>(Tm + (2 * lane + 1) * CC);
#pragma unroll
            for (int k = 0; k < 32; ++k) {
                float2 ra = rowA[k];
                float2 rb = rowB[k];
                eA[k] = bfpack(__expf(ra.x), __expf(ra.y));
                eB[k] = bfpack(__expf(rb.x), __expf(rb.y));
            }
        }
        v0 = __expf(Tm[(2 * lane) * CC + STOP_S]);
        v1 = __expf(Tm[(2 * lane + 1) * CC + STOP_S]);

        float2 ea = emb2[(size_t)(LL - 1) * 32];
        float2 eb = emb2[(size_t)(LL - 2) * 32];
        float2 ec = emb2[(size_t)(LL - 3) * 32];
        float  ma = mkb[LL - 1], mb = mkb[LL - 2], mc = mkb[LL - 3];
        __syncwarp();

        int cur = 0;
#define ADVB(t_)                                                        \
        {                                                               \
            int ti = (t_) - 2; if (ti < 0) ti = 0;                      \
            float2 en = emb2[(size_t)ti * 32];                          \
            float  mn = mkb[ti];                                        \
            ea = eb; ma = mb; eb = ec; mb = mc; ec = en; mc = mn;       \
        }
#define SB(MODE, t_)                                                    \
        {                                                               \
            float2 e0 = ea; float m0 = ma; ADVB(t_);                    \
            stepB<MODE>(e0, m0, v0, v1, S, mx, cur, vsh, eA, eB, lane); \
        }
        // 128 octets = 1024 steps: emissions LL-1 down to MID+1
#pragma unroll 1
        for (int t = LL - 2; t > MID; t -= 8) {
            SB(1, t); SB(2, t - 1); SB(0, t - 2); SB(0, t - 3);
            SB(0, t - 4); SB(0, t - 5); SB(0, t - 6); SB(0, t - 7);
        }
#undef SB
#undef ADVB
        // epilogue renorm (overflow guard for the combine)
        {
            float x = fmaxf(v0, v1);
#pragma unroll
            for (int o = 16; o; o >>= 1) x = fmaxf(x, __shfl_xor_sync(0xffffffffu, x, o));
            float r = __fdividef(1.0f, x);
            v0 *= r; v1 *= r; S += __logf(x);
        }
        warr[pair][2 * lane]     = v0;
        warr[pair][2 * lane + 1] = v1;
        if (lane == 0) sSb[pair] = S;
    }

    __syncthreads();

    if (dir == 0) {
        // logZ = log( sum_c alpha_MID[c] * w_MID[c] ) + S_f + S_b
        float term = v0 * warr[pair][2 * lane] + v1 * warr[pair][2 * lane + 1];
#pragma unroll
        for (int o = 16; o; o >>= 1) term += __shfl_xor_sync(0xffffffffu, term, o);
        if (lane == 0) g_part[b] = __logf(term) + S + sSb[pair];
    }
}

// ---------------------------------------------------------------------------
// mean(partition - scores)
// ---------------------------------------------------------------------------
__global__ void __launch_bounds__(512) finalize_kernel(float* __restrict__ out) {
    int tid = threadIdx.x;
    float d = g_part[tid] - g_scores[tid];
    __shared__ float sh[16];
#pragma unroll
    for (int o = 16; o; o >>= 1) d += __shfl_xor_sync(0xffffffffu, d, o);
    if ((tid & 31) == 0) sh[tid >> 5] = d;
    __syncthreads();
    if (tid < 16) {
        float x = sh[tid];
#pragma unroll
        for (int o = 8; o; o >>= 1) x += __shfl_xor_sync(0x0000ffffu, x, o);
        if (tid == 0) out[0] = x * (1.0f / BB);
    }
}

extern "C" void kernel_launch(void* const* d_in, const int* in_sizes, int n_in,
                              void* d_out, int out_size) {
    (void)in_sizes; (void)n_in; (void)out_size;
    const float* em   = (const float*)d_in[0];
    const float* T    = (const float*)d_in[1];
    const float* mask = (const float*)d_in[2];
    const int*   tags = (const int*)d_in[3];
    float* out = (float*)d_out;

    alpha_kernel<<<BB / 2, 160>>>(em, T, mask, tags);
    finalize_kernel<<<1, 512>>>(out);
}